// round 13
// baseline (speedup 1.0000x reference)
#include <cuda_runtime.h>
#include <cstdint>

// ---------------- problem constants ----------------
#define T_TOK   16384
#define D_DIM   2048
#define E_EXP   64
#define AUX_W   0.01f

#define BM      128
#define BK      32
#define NCHUNK  (D_DIM / BK)      // 64
#define GCH     (NCHUNK / 2)      // 32 chunks per k-group
#define THREADS 512
#define NCTA    (T_TOK / BM)      // 128
#define LPAD    68
#define TAU     5e-4f

// smem stage layout (bytes). 2 bf16 planes, row stride 80 B
// A planes: 128 x 80 = 10240 each; B planes: 64 x 80 = 5120 each
#define AP0     0
#define AP1     10240
#define BPL0    20480
#define BPL1    25600
#define STG_B   30720
#define DYN_SMEM (4 * STG_B)      // 122880 (2 groups x 2 stages)

// ---------------- global scratch ----------------
__device__ uint32_t g_Wb0[E_EXP * D_DIM / 2];
__device__ uint32_t g_Wb1[E_EXP * D_DIM / 2];
__device__ float    g_psum[NCTA * E_EXP];
__device__ float    g_pcnt[NCTA * E_EXP];
__device__ unsigned g_done = 0;

// ---------------- helpers ----------------
__device__ __forceinline__ uint32_t smem_u32(const void* p) {
    uint32_t a;
    asm("{ .reg .u64 t; cvta.to.shared.u64 t, %1; cvt.u32.u64 %0, t; }" : "=r"(a) : "l"(p));
    return a;
}
// round-to-nearest 2-way bf16 split of a float pair (x = even k -> low half)
__device__ __forceinline__ void split2_pair(float x, float y, uint32_t& p0, uint32_t& p1) {
    asm("cvt.rn.bf16x2.f32 %0, %1, %2;" : "=r"(p0) : "f"(y), "f"(x));
    float x0 = __uint_as_float(p0 << 16);
    float y0 = __uint_as_float(p0 & 0xFFFF0000u);
    float xr1 = x - x0;
    float yr1 = y - y0;
    asm("cvt.rn.bf16x2.f32 %0, %1, %2;" : "=r"(p1) : "f"(yr1), "f"(xr1));
}
__device__ __forceinline__ void sts64(uint32_t addr, uint32_t a, uint32_t b) {
    asm volatile("st.shared.v2.b32 [%0], {%1, %2};" :: "r"(addr), "r"(a), "r"(b) : "memory");
}
__device__ __forceinline__ uint32_t lds32(uint32_t addr) {
    uint32_t r;
    asm volatile("ld.shared.b32 %0, [%1];" : "=r"(r) : "r"(addr));
    return r;
}
#define CP_ASYNC16(saddr, gptr) \
    asm volatile("cp.async.cg.shared.global [%0], [%1], 16;" :: "r"(saddr), "l"(gptr) : "memory")
#define CP_COMMIT() asm volatile("cp.async.commit_group;" ::: "memory")
#define CP_WAIT0()  asm volatile("cp.async.wait_group 0;" ::: "memory")
#define BAR_GRP(id) asm volatile("bar.sync %0, 256;" :: "r"(id) : "memory")

#define MMA_BF16(c, a0, a1, a2, a3, b0, b1) \
    asm volatile("mma.sync.aligned.m16n8k16.row.col.f32.bf16.bf16.f32 " \
        "{%0,%1,%2,%3}, {%4,%5,%6,%7}, {%8,%9}, {%0,%1,%2,%3};" \
        : "+f"((c)[0]), "+f"((c)[1]), "+f"((c)[2]), "+f"((c)[3]) \
        : "r"(a0), "r"(a1), "r"(a2), "r"(a3), "r"(b0), "r"(b1))

// ---------------- W pre-split kernel ----------------
__global__ __launch_bounds__(256) void prep_kernel(const float* __restrict__ W) {
    int i = blockIdx.x * 256 + threadIdx.x;     // pair index, 65536 total
    float2 v = ((const float2*)W)[i];
    uint32_t p0, p1;
    split2_pair(v.x, v.y, p0, p1);
    g_Wb0[i] = p0;
    g_Wb1[i] = p1;
}

// ---------------- router ----------------
extern __shared__ __align__(16) float Sf[];

__global__ __launch_bounds__(THREADS, 1) void router_kernel(
    const float* __restrict__ X,
    const float* __restrict__ W,
    float* __restrict__ out)
{
    __shared__ int   sCnt[E_EXP];
    __shared__ float sRed[E_EXP];
    __shared__ int   sI1[BM];
    __shared__ int   sFlag[BM];
    __shared__ int   sNF;
    __shared__ unsigned s_last;

    const int tid   = threadIdx.x;
    const int lane  = tid & 31;
    const int wrp   = tid >> 5;       // 0..15
    const int g     = wrp >> 3;       // k-group 0/1
    const int gw    = wrp & 7;        // warp within group
    const int gt    = tid & 255;      // thread within group
    const int warpM = gw >> 1;        // 0..3 -> rows [warpM*32,+32)
    const int warpN = gw & 1;         // 0..1 -> cols [warpN*32,+32)
    const int quad  = lane >> 2;
    const int qt    = lane & 3;
    const int bid   = blockIdx.x;
    const int m0    = bid * BM;

    if (tid < E_EXP) sCnt[tid] = 0;
    if (tid == 0) sNF = 0;

    const float* Xp = X + (size_t)m0 * D_DIM;
    const uint32_t sb = smem_u32(Sf);
    const uint32_t gbase = sb + (uint32_t)(g * 2) * STG_B;

    // A slots within group: idx = gt + r*256 (r<4): row = idx>>3, c4 = idx&7
    int ar[4], ac[4];
#pragma unroll
    for (int r = 0; r < 4; r++) { int s = gt + r * 256; ar[r] = s >> 3; ac[r] = s & 7; }
    // B cp slots within group: idx = gt + r*256 (r<2): plane = idx>>8, n = (idx&255)>>2, c16 = idx&3
    int bpl[2], bn[2], bc[2];
#pragma unroll
    for (int r = 0; r < 2; r++) { int s = gt + r * 256; bpl[r] = s >> 8; bn[r] = (s & 255) >> 2; bc[r] = s & 3; }

    float4 xv[4];
    auto ldgx = [&](int j) {
        const int kt = (g * GCH + j) * BK;
#pragma unroll
        for (int r = 0; r < 4; r++) xv[r] = *(const float4*)(Xp + (size_t)ar[r] * D_DIM + kt + ac[r] * 4);
    };
    auto stsa = [&](int s) {
        const uint32_t st = gbase + (uint32_t)s * STG_B;
#pragma unroll
        for (int r = 0; r < 4; r++) {
            uint32_t base = st + (uint32_t)ar[r] * 80u + (uint32_t)ac[r] * 8u;
            uint32_t q00, q01, q10, q11;
            split2_pair(xv[r].x, xv[r].y, q00, q01);
            split2_pair(xv[r].z, xv[r].w, q10, q11);
            sts64(base + AP0, q00, q10);
            sts64(base + AP1, q01, q11);
        }
    };
    auto cpb = [&](int j, int s) {
        const int c = g * GCH + j;
        const uint32_t st = gbase + (uint32_t)s * STG_B;
#pragma unroll
        for (int r = 0; r < 2; r++) {
            const uint32_t* gsrc = (bpl[r] == 0 ? g_Wb0 : g_Wb1)
                + (size_t)bn[r] * (D_DIM / 2) + c * (BK / 2) + bc[r] * 4;
            uint32_t dst = st + BPL0 + (uint32_t)bpl[r] * 5120u + (uint32_t)bn[r] * 80u + (uint32_t)bc[r] * 16u;
            CP_ASYNC16(dst, gsrc);
        }
        CP_COMMIT();
    };

    float acc[2][4][4];
#pragma unroll
    for (int mi = 0; mi < 2; mi++)
#pragma unroll
        for (int ni = 0; ni < 4; ni++)
#pragma unroll
            for (int r = 0; r < 4; r++) acc[mi][ni][r] = 0.0f;

    // ---- prologue (per group) ----
    ldgx(0);
    stsa(0);
    cpb(0, 0);
    ldgx(1);
    CP_WAIT0();
    BAR_GRP(g + 1);

    const uint32_t aRow = (uint32_t)(warpM * 32 + quad) * 80u + (uint32_t)qt * 4u;
    const uint32_t bRow = (uint32_t)(warpN * 32 + quad) * 80u + (uint32_t)qt * 4u + BPL0;

#pragma unroll 1
    for (int j = 0; j < GCH; j++) {
        const int s = j & 1;
        const uint32_t st = gbase + (uint32_t)s * STG_B;

        if (j + 1 < GCH) { cpb(j + 1, s ^ 1); stsa(s ^ 1); }
        if (j + 2 < GCH) ldgx(j + 2);

#pragma unroll
        for (int kg = 0; kg < 4; kg++) {
            const uint32_t off = (uint32_t)kg * 16u;
            uint32_t a0[2], a1[2], a2[2], a3[2];
#pragma unroll
            for (int mi = 0; mi < 2; mi++) {
                uint32_t ab = st + aRow + (uint32_t)(mi * 16) * 80u + off;
                a0[mi] = lds32(ab + AP0);            // p0, r
                a1[mi] = lds32(ab + AP0 + 640u);     // p0, r+8
                a2[mi] = lds32(ab + AP1);            // p1, r
                a3[mi] = lds32(ab + AP1 + 640u);     // p1, r+8
            }
            uint32_t b0[4], b1[4];
#pragma unroll
            for (int ni = 0; ni < 4; ni++) {
                uint32_t bb = st + bRow + (uint32_t)(ni * 8) * 80u + off;
                b0[ni] = lds32(bb);            // q0
                b1[ni] = lds32(bb + 5120u);    // q1
            }
            // MMA1: [p0|p1] x [q0|q1] -> p0q0 + p1q1
#pragma unroll
            for (int mi = 0; mi < 2; mi++)
#pragma unroll
                for (int ni = 0; ni < 4; ni++)
                    MMA_BF16(acc[mi][ni], a0[mi], a1[mi], a2[mi], a3[mi], b0[ni], b1[ni]);
            // MMA2: [p0|p1] x [q1|q0] -> p0q1 + p1q0  (full 2-plane product captured)
#pragma unroll
            for (int mi = 0; mi < 2; mi++)
#pragma unroll
                for (int ni = 0; ni < 4; ni++)
                    MMA_BF16(acc[mi][ni], a0[mi], a1[mi], a2[mi], a3[mi], b1[ni], b0[ni]);
        }

        CP_WAIT0();
        BAR_GRP(g + 1);
    }

    // ---------- combine both groups' partial logits into Sf[128][LPAD] ----------
    __syncthreads();
    if (g == 1) {
#pragma unroll
        for (int mi = 0; mi < 2; mi++)
#pragma unroll
            for (int ni = 0; ni < 4; ni++) {
                int row = warpM * 32 + mi * 16 + quad;
                int col = warpN * 32 + ni * 8 + 2 * qt;
                *(float2*)&Sf[row * LPAD + col]       = make_float2(acc[mi][ni][0], acc[mi][ni][1]);
                *(float2*)&Sf[(row + 8) * LPAD + col] = make_float2(acc[mi][ni][2], acc[mi][ni][3]);
            }
    }
    __syncthreads();
    if (g == 0) {
#pragma unroll
        for (int mi = 0; mi < 2; mi++)
#pragma unroll
            for (int ni = 0; ni < 4; ni++) {
                int row = warpM * 32 + mi * 16 + quad;
                int col = warpN * 32 + ni * 8 + 2 * qt;
                float2 p0 = *(float2*)&Sf[row * LPAD + col];
                float2 p1 = *(float2*)&Sf[(row + 8) * LPAD + col];
                *(float2*)&Sf[row * LPAD + col]       = make_float2(p0.x + acc[mi][ni][0], p0.y + acc[mi][ni][1]);
                *(float2*)&Sf[(row + 8) * LPAD + col] = make_float2(p1.x + acc[mi][ni][2], p1.y + acc[mi][ni][3]);
            }
    }
    __syncthreads();

    // ---------- per-token approx epilogue (threads 0..127) ----------
    const bool act = tid < BM;
    float v[E_EXP];
    float l1 = -1e30f, l2 = -1e30f, l3 = -1e30f, inv = 0.0f;
    int   i1 = 0, i2 = 0;
    if (act) {
        const float* row = &Sf[tid * LPAD];
#pragma unroll
        for (int jj = 0; jj < E_EXP / 4; jj++) {
            float4 q = *(const float4*)&row[4 * jj];
            v[4 * jj] = q.x; v[4 * jj + 1] = q.y; v[4 * jj + 2] = q.z; v[4 * jj + 3] = q.w;
        }
#pragma unroll
        for (int e = 0; e < E_EXP; e++) {
            float x = v[e];
            if (x > l1)      { l3 = l2; l2 = l1; i2 = i1; l1 = x; i1 = e; }
            else if (x > l2) { l3 = l2; l2 = x;  i2 = e; }
            else if (x > l3) { l3 = x; }
        }
        float ssum = 0.0f;
#pragma unroll
        for (int e = 0; e < E_EXP; e++) { float p = __expf(v[e] - l1); ssum += p; v[e] = p; }
        inv = 1.0f / ssum;
    }
    __syncthreads();   // all logit reads done before packed-prob overwrite
    if (act) {
#pragma unroll
        for (int jj = 0; jj < E_EXP / 4; jj++) {
            float4 q = make_float4(v[4 * jj] * inv, v[4 * jj + 1] * inv, v[4 * jj + 2] * inv, v[4 * jj + 3] * inv);
            *(float4*)&Sf[tid * E_EXP + 4 * jj] = q;
        }
        float e2 = __expf(l2 - l1);
        float dn = 1.0f / (1.0f + e2);
        int gm = m0 + tid;
        out[2 * gm + 0] = (float)i1;
        out[2 * gm + 1] = (float)i2;
        out[2 * T_TOK + 2 * gm + 0] = dn;
        out[2 * T_TOK + 2 * gm + 1] = e2 * dn;
        sI1[tid] = i1;
        if ((l1 - l2 < TAU) || (l2 - l3 < TAU)) {
            int fi = atomicAdd(&sNF, 1);
            sFlag[fi] = tid;
        }
    }
    __syncthreads();

    // ---------- exact fp32 rescue of flagged tokens (one warp per token) ----------
    {
        const int nf = sNF;
        for (int f = wrp; f < nf; f += 16) {
            const int t  = sFlag[f];
            const int gm = m0 + t;
            const float* xr = X + (size_t)gm * D_DIM;
            const float* w0 = W + (size_t)lane * D_DIM;
            const float* w1 = W + (size_t)(lane + 32) * D_DIM;
            float d0 = 0.0f, d1 = 0.0f;
#pragma unroll 4
            for (int jj = 0; jj < D_DIM / 4; jj++) {
                float4 xq = ((const float4*)xr)[jj];
                float4 wa = ((const float4*)w0)[jj];
                float4 wb = ((const float4*)w1)[jj];
                d0 = fmaf(xq.x, wa.x, d0); d0 = fmaf(xq.y, wa.y, d0);
                d0 = fmaf(xq.z, wa.z, d0); d0 = fmaf(xq.w, wa.w, d0);
                d1 = fmaf(xq.x, wb.x, d1); d1 = fmaf(xq.y, wb.y, d1);
                d1 = fmaf(xq.z, wb.z, d1); d1 = fmaf(xq.w, wb.w, d1);
            }
            // per-lane sorted top-2 of its two experts (lower index = lane, wins ties)
            float m1, m2; int j1, j2;
            if (d1 > d0) { m1 = d1; j1 = lane + 32; m2 = d0; j2 = lane; }
            else         { m1 = d0; j1 = lane;      m2 = d1; j2 = lane + 32; }
            // warp top-2 reduction
#pragma unroll
            for (int o = 16; o > 0; o >>= 1) {
                float b1v = __shfl_xor_sync(0xFFFFFFFF, m1, o);
                int   bj1 = __shfl_xor_sync(0xFFFFFFFF, j1, o);
                float b2v = __shfl_xor_sync(0xFFFFFFFF, m2, o);
                int   bj2 = __shfl_xor_sync(0xFFFFFFFF, j2, o);
                if (b1v > m1 || (b1v == m1 && bj1 < j1)) {
                    if (m1 > b2v || (m1 == b2v && j1 < bj2)) { m2 = m1; j2 = j1; }
                    else                                     { m2 = b2v; j2 = bj2; }
                    m1 = b1v; j1 = bj1;
                } else {
                    if (b1v > m2 || (b1v == m2 && bj1 < j2)) { m2 = b1v; j2 = bj1; }
                }
            }
            if (lane == 0) {
                float e2 = __expf(m2 - m1);
                float dn = 1.0f / (1.0f + e2);
                out[2 * gm + 0] = (float)j1;
                out[2 * gm + 1] = (float)j2;
                out[2 * T_TOK + 2 * gm + 0] = dn;
                out[2 * T_TOK + 2 * gm + 1] = e2 * dn;
                sI1[t] = j1;
            }
        }
    }
    __syncthreads();

    // ---------- counts (post-rescue) + per-expert partials ----------
    if (tid < BM) atomicAdd(&sCnt[sI1[tid]], 1);
    __syncthreads();

    if (tid < E_EXP) {
        float s = 0.0f;
#pragma unroll 8
        for (int m = 0; m < BM; m++) s += Sf[m * E_EXP + tid];
        g_psum[bid * E_EXP + tid] = s;
        g_pcnt[bid * E_EXP + tid] = (float)sCnt[tid];
    }
    __threadfence();
    __syncthreads();

    if (tid == 0) s_last = (atomicInc(&g_done, NCTA - 1) == NCTA - 1) ? 1u : 0u;
    __syncthreads();

    if (s_last) {
        __threadfence();
        if (tid < E_EXP) {
            float a = 0.0f, cn = 0.0f;
#pragma unroll 8
            for (int b = 0; b < NCTA; b++) {
                a  += __ldcg(&g_psum[b * E_EXP + tid]);
                cn += __ldcg(&g_pcnt[b * E_EXP + tid]);
            }
            float invT = 1.0f / (float)T_TOK;
            sRed[tid] = (cn * invT) * (a * invT);
        }
        __syncthreads();
        if (tid < 32) {
            float vv = sRed[tid] + sRed[tid + 32];
#pragma unroll
            for (int o = 16; o > 0; o >>= 1) vv += __shfl_xor_sync(0xFFFFFFFF, vv, o);
            if (tid == 0) out[4 * T_TOK] = (float)E_EXP * AUX_W * vv;
        }
    }
}

extern "C" void kernel_launch(void* const* d_in, const int* in_sizes, int n_in,
                              void* d_out, int out_size) {
    const float* X = (const float*)d_in[0];
    const float* W = (const float*)d_in[1];
    float* out = (float*)d_out;

    prep_kernel<<<256, 256>>>(W);
    cudaFuncSetAttribute(router_kernel, cudaFuncAttributeMaxDynamicSharedMemorySize, DYN_SMEM);
    router_kernel<<<NCTA, THREADS, DYN_SMEM>>>(X, W, out);
}

// round 15
// speedup vs baseline: 1.6855x; 1.6855x over previous
#include <cuda_runtime.h>
#include <cstdint>

// ---------------- problem constants ----------------
#define T_TOK   16384
#define D_DIM   2048
#define E_EXP   64
#define AUX_W   0.01f

#define BM      128
#define BK      32
#define NCHUNK  (D_DIM / BK)      // 64
#define THREADS 256
#define NCTA    (T_TOK / BM)      // 128
#define LPAD    68
#define TAU     1e-4f

// smem stage layout (bytes). 2 bf16 planes, row stride 80 B
// A planes: 128 x 80 = 10240 each; B planes: 64 x 80 = 5120 each
#define AP0     0
#define AP1     10240
#define BPL0    20480
#define BPL1    25600
#define STG_B   30720
#define DYN_SMEM (2 * STG_B)      // 61440

// ---------------- global scratch ----------------
__device__ uint32_t g_Wb0[E_EXP * D_DIM / 2];
__device__ uint32_t g_Wb1[E_EXP * D_DIM / 2];
__device__ float    g_psum[NCTA * E_EXP];
__device__ float    g_pcnt[NCTA * E_EXP];
__device__ unsigned g_done = 0;

// ---------------- helpers ----------------
__device__ __forceinline__ uint32_t smem_u32(const void* p) {
    uint32_t a;
    asm("{ .reg .u64 t; cvta.to.shared.u64 t, %1; cvt.u32.u64 %0, t; }" : "=r"(a) : "l"(p));
    return a;
}
// round-to-nearest 2-way bf16 split of a float pair (x = even k -> low half)
__device__ __forceinline__ void split2_pair(float x, float y, uint32_t& p0, uint32_t& p1) {
    asm("cvt.rn.bf16x2.f32 %0, %1, %2;" : "=r"(p0) : "f"(y), "f"(x));
    float x0 = __uint_as_float(p0 << 16);
    float y0 = __uint_as_float(p0 & 0xFFFF0000u);
    float xr1 = x - x0;
    float yr1 = y - y0;
    asm("cvt.rn.bf16x2.f32 %0, %1, %2;" : "=r"(p1) : "f"(yr1), "f"(xr1));
}
__device__ __forceinline__ void sts64(uint32_t addr, uint32_t a, uint32_t b) {
    asm volatile("st.shared.v2.b32 [%0], {%1, %2};" :: "r"(addr), "r"(a), "r"(b) : "memory");
}
__device__ __forceinline__ uint32_t lds32(uint32_t addr) {
    uint32_t r;
    asm volatile("ld.shared.b32 %0, [%1];" : "=r"(r) : "r"(addr));
    return r;
}
#define CP_ASYNC16(saddr, gptr) \
    asm volatile("cp.async.cg.shared.global [%0], [%1], 16;" :: "r"(saddr), "l"(gptr) : "memory")
#define CP_COMMIT() asm volatile("cp.async.commit_group;" ::: "memory")
#define CP_WAIT0()  asm volatile("cp.async.wait_group 0;" ::: "memory")

#define MMA_BF16(c, a0, a1, a2, a3, b0, b1) \
    asm volatile("mma.sync.aligned.m16n8k16.row.col.f32.bf16.bf16.f32 " \
        "{%0,%1,%2,%3}, {%4,%5,%6,%7}, {%8,%9}, {%0,%1,%2,%3};" \
        : "+f"((c)[0]), "+f"((c)[1]), "+f"((c)[2]), "+f"((c)[3]) \
        : "r"(a0), "r"(a1), "r"(a2), "r"(a3), "r"(b0), "r"(b1))

// ---------------- W pre-split kernel ----------------
__global__ __launch_bounds__(256) void prep_kernel(const float* __restrict__ W) {
    int i = blockIdx.x * 256 + threadIdx.x;     // pair index, 65536 total
    float2 v = ((const float2*)W)[i];
    uint32_t p0, p1;
    split2_pair(v.x, v.y, p0, p1);
    g_Wb0[i] = p0;
    g_Wb1[i] = p1;
}

// ---------------- router ----------------
extern __shared__ __align__(16) float Sf[];

__global__ __launch_bounds__(THREADS, 1) void router_kernel(
    const float* __restrict__ X,
    const float* __restrict__ W,
    float* __restrict__ out)
{
    __shared__ int   sCnt[E_EXP];
    __shared__ float sRed[E_EXP];
    __shared__ int   sI1[BM];
    __shared__ int   sFlagT[BM];
    __shared__ float sFlagP[BM];
    __shared__ int   sNF;
    __shared__ unsigned s_last;

    const int tid   = threadIdx.x;
    const int lane  = tid & 31;
    const int wrp   = tid >> 5;       // 0..7
    const int warpM = wrp >> 1;       // 0..3 -> rows [warpM*32,+32)
    const int warpN = wrp & 1;        // 0..1 -> cols [warpN*32,+32)
    const int quad  = lane >> 2;
    const int qt    = lane & 3;
    const int bid   = blockIdx.x;
    const int m0    = bid * BM;

    if (tid < E_EXP) sCnt[tid] = 0;
    if (tid == 0) sNF = 0;

    const float* Xp = X + (size_t)m0 * D_DIM;
    const uint32_t sb = smem_u32(Sf);

    // A slots: idx = tid + r*256 (r<4): row = idx>>3, c4 = idx&7
    int ar[4], ac[4];
#pragma unroll
    for (int r = 0; r < 4; r++) { int s = tid + r * THREADS; ar[r] = s >> 3; ac[r] = s & 7; }
    // B cp slots: idx = tid + r*256 (r<2): plane = idx>>8, n = (idx&255)>>2, c16 = idx&3
    int bpl[2], bn[2], bc[2];
#pragma unroll
    for (int r = 0; r < 2; r++) { int s = tid + r * THREADS; bpl[r] = s >> 8; bn[r] = (s & 255) >> 2; bc[r] = s & 3; }

    float4 xv[4];
    auto ldgx = [&](int i) {
        const int kt = i * BK;
#pragma unroll
        for (int r = 0; r < 4; r++) xv[r] = *(const float4*)(Xp + (size_t)ar[r] * D_DIM + kt + ac[r] * 4);
    };
    auto stsa = [&](int s) {
        const uint32_t st = sb + (uint32_t)s * STG_B;
#pragma unroll
        for (int r = 0; r < 4; r++) {
            uint32_t base = st + (uint32_t)ar[r] * 80u + (uint32_t)ac[r] * 8u;
            uint32_t q00, q01, q10, q11;
            split2_pair(xv[r].x, xv[r].y, q00, q01);
            split2_pair(xv[r].z, xv[r].w, q10, q11);
            sts64(base + AP0, q00, q10);
            sts64(base + AP1, q01, q11);
        }
    };
    auto cpb = [&](int i, int s) {
        const uint32_t st = sb + (uint32_t)s * STG_B;
#pragma unroll
        for (int r = 0; r < 2; r++) {
            const uint32_t* gsrc = (bpl[r] == 0 ? g_Wb0 : g_Wb1)
                + (size_t)bn[r] * (D_DIM / 2) + i * (BK / 2) + bc[r] * 4;
            uint32_t dst = st + BPL0 + (uint32_t)bpl[r] * 5120u + (uint32_t)bn[r] * 80u + (uint32_t)bc[r] * 16u;
            CP_ASYNC16(dst, gsrc);
        }
        CP_COMMIT();
    };

    // dual accumulators: accA for MMA1 (p0q0+p1q1), accB for MMA2 (p0q1+p1q0)
    float accA[2][4][4], accB[2][4][4];
#pragma unroll
    for (int mi = 0; mi < 2; mi++)
#pragma unroll
        for (int ni = 0; ni < 4; ni++)
#pragma unroll
            for (int r = 0; r < 4; r++) { accA[mi][ni][r] = 0.0f; accB[mi][ni][r] = 0.0f; }

    // ---- prologue ----
    ldgx(0);
    stsa(0);
    cpb(0, 0);
    ldgx(1);
    CP_WAIT0();
    __syncthreads();

    const uint32_t aRow = (uint32_t)(warpM * 32 + quad) * 80u + (uint32_t)qt * 4u;
    const uint32_t bRow = (uint32_t)(warpN * 32 + quad) * 80u + (uint32_t)qt * 4u + BPL0;

#pragma unroll 1
    for (int i = 0; i < NCHUNK; i++) {
        const int s = i & 1;
        const uint32_t st = sb + (uint32_t)s * STG_B;

        if (i + 1 < NCHUNK) { cpb(i + 1, s ^ 1); stsa(s ^ 1); }
        if (i + 2 < NCHUNK) ldgx(i + 2);

#pragma unroll
        for (int kg = 0; kg < 4; kg++) {
            const uint32_t off = (uint32_t)kg * 16u;
            uint32_t a0[2], a1[2], a2[2], a3[2];
#pragma unroll
            for (int mi = 0; mi < 2; mi++) {
                uint32_t ab = st + aRow + (uint32_t)(mi * 16) * 80u + off;
                a0[mi] = lds32(ab + AP0);
                a1[mi] = lds32(ab + AP0 + 640u);
                a2[mi] = lds32(ab + AP1);
                a3[mi] = lds32(ab + AP1 + 640u);
            }
            uint32_t b0[4], b1[4];
#pragma unroll
            for (int ni = 0; ni < 4; ni++) {
                uint32_t bb = st + bRow + (uint32_t)(ni * 8) * 80u + off;
                b0[ni] = lds32(bb);
                b1[ni] = lds32(bb + 5120u);
            }
            // MMA1 -> accA (independent of MMA2)
#pragma unroll
            for (int mi = 0; mi < 2; mi++)
#pragma unroll
                for (int ni = 0; ni < 4; ni++)
                    MMA_BF16(accA[mi][ni], a0[mi], a1[mi], a2[mi], a3[mi], b0[ni], b1[ni]);
            // MMA2 -> accB (B regs swapped; no RAW with MMA1)
#pragma unroll
            for (int mi = 0; mi < 2; mi++)
#pragma unroll
                for (int ni = 0; ni < 4; ni++)
                    MMA_BF16(accB[mi][ni], a0[mi], a1[mi], a2[mi], a3[mi], b1[ni], b0[ni]);
        }

        CP_WAIT0();
        __syncthreads();
    }

    // ---------- write logits (accA+accB) to smem [128][LPAD] ----------
#pragma unroll
    for (int mi = 0; mi < 2; mi++)
#pragma unroll
        for (int ni = 0; ni < 4; ni++) {
            int row = warpM * 32 + mi * 16 + quad;
            int col = warpN * 32 + ni * 8 + 2 * qt;
            *(float2*)&Sf[row * LPAD + col] =
                make_float2(accA[mi][ni][0] + accB[mi][ni][0], accA[mi][ni][1] + accB[mi][ni][1]);
            *(float2*)&Sf[(row + 8) * LPAD + col] =
                make_float2(accA[mi][ni][2] + accB[mi][ni][2], accA[mi][ni][3] + accB[mi][ni][3]);
        }
    __syncthreads();

    // ---------- per-token approx epilogue (threads 0..127) ----------
    const bool act = tid < BM;
    float v[E_EXP];
    float l1 = -1e30f, l2 = -1e30f, l3 = -1e30f, inv = 0.0f;
    int   i1 = 0, i2 = 0;
    if (act) {
        const float* row = &Sf[tid * LPAD];
#pragma unroll
        for (int jj = 0; jj < E_EXP / 4; jj++) {
            float4 q = *(const float4*)&row[4 * jj];
            v[4 * jj] = q.x; v[4 * jj + 1] = q.y; v[4 * jj + 2] = q.z; v[4 * jj + 3] = q.w;
        }
#pragma unroll
        for (int e = 0; e < E_EXP; e++) {
            float x = v[e];
            if (x > l1)      { l3 = l2; l2 = l1; i2 = i1; l1 = x; i1 = e; }
            else if (x > l2) { l3 = l2; l2 = x;  i2 = e; }
            else if (x > l3) { l3 = x; }
        }
        float ssum = 0.0f;
#pragma unroll
        for (int e = 0; e < E_EXP; e++) { float p = __expf(v[e] - l1); ssum += p; v[e] = p; }
        inv = 1.0f / ssum;
    }
    __syncthreads();   // logits fully read before packed-prob overwrite
    if (act) {
#pragma unroll
        for (int jj = 0; jj < E_EXP / 4; jj++) {
            float4 q = make_float4(v[4 * jj] * inv, v[4 * jj + 1] * inv, v[4 * jj + 2] * inv, v[4 * jj + 3] * inv);
            *(float4*)&Sf[tid * E_EXP + 4 * jj] = q;
        }
        float e2 = __expf(l2 - l1);
        float dn = 1.0f / (1.0f + e2);
        int gm = m0 + tid;
        out[2 * gm + 0] = (float)i1;
        out[2 * gm + 1] = (float)i2;
        out[2 * T_TOK + 2 * gm + 0] = dn;
        out[2 * T_TOK + 2 * gm + 1] = e2 * dn;
        sI1[tid] = i1;
        if ((l1 - l2 < TAU) || (l2 - l3 < TAU)) {
            int fi = atomicAdd(&sNF, 1);
            sFlagT[fi] = tid;
            sFlagP[fi] = __expf(l2 - TAU - l1) * inv;   // prob-space candidate threshold
        }
    }
    __syncthreads();

    // ---------- exact rescue: candidate-set fp32 dots, warp-parallel over k ----------
    {
        const int nf = sNF;
        for (int f = wrp; f < nf; f += 8) {
            const int t    = sFlagT[f];
            const float pt = sFlagP[f];
            const int gm   = m0 + t;
            // candidate masks from normalized probs (monotone in logits)
            float pe0 = Sf[t * E_EXP + lane];
            float pe1 = Sf[t * E_EXP + 32 + lane];
            unsigned mm0 = __ballot_sync(0xFFFFFFFF, pe0 >= pt);
            unsigned mm1 = __ballot_sync(0xFFFFFFFF, pe1 >= pt);
            const float4* xr = (const float4*)(X + (size_t)gm * D_DIM);
            float m1 = -1e30f, m2 = -1e30f;
            int   j1 = 0, j2 = 0;
            while (mm0 | mm1) {
                int e;
                if (mm0) { e = __ffs(mm0) - 1; mm0 &= mm0 - 1; }
                else     { e = 32 + __ffs(mm1) - 1; mm1 &= mm1 - 1; }
                const float4* wr = (const float4*)(W + (size_t)e * D_DIM);
                float s0 = 0.0f, s1 = 0.0f;
#pragma unroll
                for (int ii = 0; ii < 16; ii += 2) {
                    float4 xa = xr[lane + 32 * ii],       wa = wr[lane + 32 * ii];
                    float4 xb = xr[lane + 32 * (ii + 1)], wb = wr[lane + 32 * (ii + 1)];
                    s0 = fmaf(xa.x, wa.x, s0); s0 = fmaf(xa.y, wa.y, s0);
                    s0 = fmaf(xa.z, wa.z, s0); s0 = fmaf(xa.w, wa.w, s0);
                    s1 = fmaf(xb.x, wb.x, s1); s1 = fmaf(xb.y, wb.y, s1);
                    s1 = fmaf(xb.z, wb.z, s1); s1 = fmaf(xb.w, wb.w, s1);
                }
                float sv = s0 + s1;
#pragma unroll
                for (int o = 16; o > 0; o >>= 1) sv += __shfl_xor_sync(0xFFFFFFFF, sv, o);
                // candidates processed in increasing e; strict > keeps lowest index on ties
                if (sv > m1)      { m2 = m1; j2 = j1; m1 = sv; j1 = e; }
                else if (sv > m2) { m2 = sv; j2 = e; }
            }
            if (lane == 0) {
                float e2 = __expf(m2 - m1);
                float dn = 1.0f / (1.0f + e2);
                out[2 * gm + 0] = (float)j1;
                out[2 * gm + 1] = (float)j2;
                out[2 * T_TOK + 2 * gm + 0] = dn;
                out[2 * T_TOK + 2 * gm + 1] = e2 * dn;
                sI1[t] = j1;
            }
        }
    }
    __syncthreads();

    // ---------- counts (post-rescue) + per-expert partials ----------
    if (tid < BM) atomicAdd(&sCnt[sI1[tid]], 1);
    __syncthreads();

    if (tid < E_EXP) {
        float s = 0.0f;
#pragma unroll 8
        for (int m = 0; m < BM; m++) s += Sf[m * E_EXP + tid];
        g_psum[bid * E_EXP + tid] = s;
        g_pcnt[bid * E_EXP + tid] = (float)sCnt[tid];
    }
    __threadfence();
    __syncthreads();

    if (tid == 0) s_last = (atomicInc(&g_done, NCTA - 1) == NCTA - 1) ? 1u : 0u;
    __syncthreads();

    if (s_last) {
        __threadfence();
        if (tid < E_EXP) {
            float a = 0.0f, cn = 0.0f;
#pragma unroll 8
            for (int b = 0; b < NCTA; b++) {
                a  += __ldcg(&g_psum[b * E_EXP + tid]);
                cn += __ldcg(&g_pcnt[b * E_EXP + tid]);
            }
            float invT = 1.0f / (float)T_TOK;
            sRed[tid] = (cn * invT) * (a * invT);
        }
        __syncthreads();
        if (tid < 32) {
            float vv = sRed[tid] + sRed[tid + 32];
#pragma unroll
            for (int o = 16; o > 0; o >>= 1) vv += __shfl_xor_sync(0xFFFFFFFF, vv, o);
            if (tid == 0) out[4 * T_TOK] = (float)E_EXP * AUX_W * vv;
        }
    }
}

extern "C" void kernel_launch(void* const* d_in, const int* in_sizes, int n_in,
                              void* d_out, int out_size) {
    const float* X = (const float*)d_in[0];
    const float* W = (const float*)d_in[1];
    float* out = (float*)d_out;

    prep_kernel<<<256, 256>>>(W);
    cudaFuncSetAttribute(router_kernel, cudaFuncAttributeMaxDynamicSharedMemorySize, DYN_SMEM);
    router_kernel<<<NCTA, THREADS, DYN_SMEM>>>(X, W, out);
}